// round 1
// baseline (speedup 1.0000x reference)
#include <cuda_runtime.h>

#define S_LEN 512
#define BATCH 2048
#define DIN 64
#define HID 128

#define RPW 4                    // rows per warp
#define WPC 4                    // warps per CTA
#define RPC (RPW * WPC)          // 16 rows per CTA
#define NTHREADS (WPC * 32)      // 128
#define NCTA (BATCH / RPC)       // 128

struct __align__(16) Smem {
    float wih_t[DIN][HID];            // 32 KB, transposed W_ih
    float whh_t[HID][HID];            // 64 KB, transposed W_hh
    float xs[2][WPC][RPW][DIN];       // 8 KB, double-buffered x staging
    float as[WPC][RPW][HID];          // 8 KB, a staging for GEMM2 broadcast
};

__device__ __forceinline__ float fast_tanh(float v) {
    // tanh(x) = 1 - 2/(exp(2x)+1); __expf/__fdividef rel err ~1e-6
    float e = __expf(2.0f * v);
    return 1.0f - __fdividef(2.0f, e + 1.0f);
}

__global__ void __launch_bounds__(NTHREADS, 1)
rnn_kernel(const float* __restrict__ x, const float* __restrict__ h0,
           const float* __restrict__ Wih, const float* __restrict__ bih,
           const float* __restrict__ Whh, const float* __restrict__ bhh,
           float* __restrict__ out)
{
    extern __shared__ Smem smem_raw[];
    Smem& s = smem_raw[0];

    const int tid  = threadIdx.x;
    const int warp = tid >> 5;
    const int lane = tid & 31;
    const int j0   = lane << 2;                       // this lane's 4 output cols
    const int warpRow0 = blockIdx.x * RPC + warp * RPW;

    // ---- stage transposed weights (one-time; bank conflicts OK here) ----
    for (int idx = tid; idx < HID * DIN; idx += NTHREADS) {
        int j = idx / DIN, k = idx - j * DIN;         // coalesced global read
        s.wih_t[k][j] = Wih[idx];
    }
    for (int idx = tid; idx < HID * HID; idx += NTHREADS) {
        int j = idx >> 7, k = idx & 127;
        s.whh_t[k][j] = Whh[idx];
    }

    const float4 bi = *(const float4*)(bih + j0);
    const float4 bh = *(const float4*)(bhh + j0);

    // ---- h in registers: 4 rows x 4 cols per lane ----
    float h[RPW][4];
    #pragma unroll
    for (int r = 0; r < RPW; ++r) {
        float4 hv = *(const float4*)(h0 + (size_t)(warpRow0 + r) * HID + j0);
        h[r][0] = hv.x; h[r][1] = hv.y; h[r][2] = hv.z; h[r][3] = hv.w;
    }
    __syncthreads();

    // ---- prefetch x for t=0 (4 rows x 64 floats = contiguous 1KB per warp) ----
    float4 xn0, xn1;
    {
        const float4* p = (const float4*)(x + (size_t)warpRow0 * DIN);
        xn0 = p[lane]; xn1 = p[lane + 32];
    }

    for (int t = 0; t < S_LEN; ++t) {
        const int buf = t & 1;

        // commit staged x, then prefetch t+1
        {
            float4* xs4 = (float4*)&s.xs[buf][warp][0][0];
            xs4[lane] = xn0; xs4[lane + 32] = xn1;
        }
        __syncwarp();
        {
            const int tn = (t + 1 < S_LEN) ? t + 1 : t;
            const float4* p = (const float4*)(x + ((size_t)tn * BATCH + warpRow0) * DIN);
            xn0 = p[lane]; xn1 = p[lane + 32];
        }

        // ---- GEMM1: acc = x_t @ W_ih^T + b_ih ----
        float acc[RPW][4];
        #pragma unroll
        for (int r = 0; r < RPW; ++r) {
            acc[r][0] = bi.x; acc[r][1] = bi.y; acc[r][2] = bi.z; acc[r][3] = bi.w;
        }
        #pragma unroll 2
        for (int k4 = 0; k4 < DIN / 4; ++k4) {
            float xv[RPW][4];
            #pragma unroll
            for (int r = 0; r < RPW; ++r)
                *(float4*)xv[r] = *(const float4*)&s.xs[buf][warp][r][k4 * 4];
            #pragma unroll
            for (int kk = 0; kk < 4; ++kk) {
                const float4 w = *(const float4*)&s.wih_t[k4 * 4 + kk][j0];
                #pragma unroll
                for (int r = 0; r < RPW; ++r) {
                    acc[r][0] = fmaf(xv[r][kk], w.x, acc[r][0]);
                    acc[r][1] = fmaf(xv[r][kk], w.y, acc[r][1]);
                    acc[r][2] = fmaf(xv[r][kk], w.z, acc[r][2]);
                    acc[r][3] = fmaf(xv[r][kk], w.w, acc[r][3]);
                }
            }
        }

        // ---- a = acc * h ; stage a to smem for warp broadcast ----
        float a[RPW][4];
        #pragma unroll
        for (int r = 0; r < RPW; ++r) {
            a[r][0] = acc[r][0] * h[r][0];
            a[r][1] = acc[r][1] * h[r][1];
            a[r][2] = acc[r][2] * h[r][2];
            a[r][3] = acc[r][3] * h[r][3];
            *(float4*)&s.as[warp][r][j0] = make_float4(a[r][0], a[r][1], a[r][2], a[r][3]);
        }
        __syncwarp();

        // ---- GEMM2: acc2 = a @ W_hh^T + b_hh ----
        float acc2[RPW][4];
        #pragma unroll
        for (int r = 0; r < RPW; ++r) {
            acc2[r][0] = bh.x; acc2[r][1] = bh.y; acc2[r][2] = bh.z; acc2[r][3] = bh.w;
        }
        #pragma unroll 2
        for (int k4 = 0; k4 < HID / 4; ++k4) {
            float av[RPW][4];
            #pragma unroll
            for (int r = 0; r < RPW; ++r)
                *(float4*)av[r] = *(const float4*)&s.as[warp][r][k4 * 4];
            #pragma unroll
            for (int kk = 0; kk < 4; ++kk) {
                const float4 w = *(const float4*)&s.whh_t[k4 * 4 + kk][j0];
                #pragma unroll
                for (int r = 0; r < RPW; ++r) {
                    acc2[r][0] = fmaf(av[r][kk], w.x, acc2[r][0]);
                    acc2[r][1] = fmaf(av[r][kk], w.y, acc2[r][1]);
                    acc2[r][2] = fmaf(av[r][kk], w.z, acc2[r][2]);
                    acc2[r][3] = fmaf(av[r][kk], w.w, acc2[r][3]);
                }
            }
        }

        // ---- h' = tanh(a + acc2 * h) ----
        #pragma unroll
        for (int r = 0; r < RPW; ++r) {
            h[r][0] = fast_tanh(fmaf(acc2[r][0], h[r][0], a[r][0]));
            h[r][1] = fast_tanh(fmaf(acc2[r][1], h[r][1], a[r][1]));
            h[r][2] = fast_tanh(fmaf(acc2[r][2], h[r][2], a[r][2]));
            h[r][3] = fast_tanh(fmaf(acc2[r][3], h[r][3], a[r][3]));
        }
    }

    // ---- write final hidden state ----
    #pragma unroll
    for (int r = 0; r < RPW; ++r)
        *(float4*)(out + (size_t)(warpRow0 + r) * HID + j0) =
            make_float4(h[r][0], h[r][1], h[r][2], h[r][3]);
}

extern "C" void kernel_launch(void* const* d_in, const int* in_sizes, int n_in,
                              void* d_out, int out_size)
{
    const float* x   = (const float*)d_in[0];
    const float* h0  = (const float*)d_in[1];
    const float* Wih = (const float*)d_in[2];
    const float* bih = (const float*)d_in[3];
    const float* Whh = (const float*)d_in[4];
    const float* bhh = (const float*)d_in[5];

    cudaFuncSetAttribute(rnn_kernel, cudaFuncAttributeMaxDynamicSharedMemorySize,
                         (int)sizeof(Smem));
    rnn_kernel<<<NCTA, NTHREADS, sizeof(Smem)>>>(x, h0, Wih, bih, Whh, bhh,
                                                 (float*)d_out);
}